// round 16
// baseline (speedup 1.0000x reference)
#include <cuda_runtime.h>
#include <math.h>
#include <stdint.h>

#define N_NODES 12800
#define N_EDGES 204800
#define DIM 16

typedef unsigned long long ull;

// ---------------- scratch (static device memory, no allocs) ----------------
__device__ float g_out[N_NODES * DIM];
__device__ float g_hs[N_EDGES * DIM];       // edge hidden, src-sorted order
__device__ int   g_qs[N_EDGES];             // src-sorted slot -> dst-sorted slot
__device__ float g_msg0[N_EDGES * DIM];     // message ping-pong (dst-sorted)
__device__ float g_msg1[N_EDGES * DIM];
__device__ ull   g_w2p[2048];               // w2 packed: [d][k][jj-pair] ull
__device__ int   g_src_cnt[N_NODES];        // zero at load; re-zeroed by k_scan
__device__ int   g_dst_cnt[N_NODES];        // zero at load; re-zeroed by k_scan
__device__ int   g_src_off[N_NODES + 1];
__device__ int   g_dst_off[N_NODES + 1];
__device__ int   g_src_cur[N_NODES];
__device__ int   g_dst_cur[N_NODES];
__device__ float g_invdeg[N_NODES];

// ---------------- setup ----------------
// blocks [0,800): edge histograms; blocks [800,1600): lin0.
__global__ void k_hist(const float* __restrict__ x, const int* __restrict__ ei,
                       const float* __restrict__ l0w, const float* __restrict__ l0b) {
    int gb = blockIdx.x;
    if (gb < N_EDGES / 256) {
        int e = gb * 256 + threadIdx.x;
        atomicAdd(&g_src_cnt[ei[e]], 1);
        atomicAdd(&g_dst_cnt[ei[N_EDGES + e]], 1);
    } else {
        int i = (gb - N_EDGES / 256) * 256 + threadIdx.x;
        int n = i >> 4, k = i & 15;
        float acc = l0b[k];
#pragma unroll
        for (int c = 0; c < 3; ++c) acc += x[n * 3 + c] * l0w[k * 3 + c];
        g_out[i] = fmaxf(acc, 0.0f);
    }
}

// block 0: src-count scan; block 1: dst-count scan (+invdeg); block 2: pack w2.
// Blocks 0/1 re-zero their count arrays for the next kernel_launch call.
__global__ void k_scan(const float* __restrict__ w2) {
    int tid = threadIdx.x, lane = tid & 31, wid = tid >> 5;
    if (blockIdx.x == 2) {
        // pack w2 into [d][k][jj-pair] ull layout
        for (int i = tid; i < 2048; i += 1024) {
            int d = i >> 7, k = (i >> 3) & 15, jj = i & 7;
            float lo = w2[d * 256 + k * 16 + jj * 2];
            float hi = w2[d * 256 + k * 16 + jj * 2 + 1];
            ull v;
            asm("mov.b64 %0,{%1,%2};" : "=l"(v) : "f"(lo), "f"(hi));
            g_w2p[i] = v;
        }
        return;
    }
    const int PER = 13;
    int which = blockIdx.x;
    int* cnt = which ? g_dst_cnt : g_src_cnt;
    int* off = which ? g_dst_off : g_src_off;
    int* cur = which ? g_dst_cur : g_src_cur;
    int base = tid * PER;
    int c[PER];
    int local = 0;
#pragma unroll
    for (int i = 0; i < PER; ++i) {
        int idx = base + i;
        c[i] = (idx < N_NODES) ? cnt[idx] : 0;
        local += c[i];
    }
    int incl = local;
#pragma unroll
    for (int s = 1; s < 32; s <<= 1) {
        int v = __shfl_up_sync(0xffffffffu, incl, s);
        if (lane >= s) incl += v;
    }
    __shared__ int wsum[32];
    if (lane == 31) wsum[wid] = incl;
    __syncthreads();
    if (wid == 0) {
        int v = wsum[lane], iv = v;
#pragma unroll
        for (int s = 1; s < 32; s <<= 1) {
            int t = __shfl_up_sync(0xffffffffu, iv, s);
            if (lane >= s) iv += t;
        }
        wsum[lane] = iv - v;
    }
    __syncthreads();
    int run = wsum[wid] + (incl - local);
#pragma unroll
    for (int i = 0; i < PER; ++i) {
        int idx = base + i;
        if (idx < N_NODES) {
            off[idx] = run;
            cur[idx] = run;
            if (which) g_invdeg[idx] = 1.0f / fmaxf((float)c[i], 1.0f);
            cnt[idx] = 0;                    // re-zero for next call
            run += c[i];
        }
    }
    if (tid == 1023) off[N_NODES] = run;
}

// Per edge: place into src-sorted slot p, record its dst-sorted slot q,
// compute edge hidden h = relu(ea @ nn1_w^T + nn1_b) directly into g_hs[p].
__global__ void k_scatter(const int* __restrict__ ei, const float* __restrict__ ea,
                          const float* __restrict__ n1w, const float* __restrict__ n1b) {
    int e = blockIdx.x * blockDim.x + threadIdx.x;
    if (e >= N_EDGES) return;
    int s = ei[e], d = ei[N_EDGES + e];
    int p = atomicAdd(&g_src_cur[s], 1);
    int q = atomicAdd(&g_dst_cur[d], 1);
    g_qs[p] = q;
    float4 a = __ldg((const float4*)&ea[e * 4]);
    float* hd = &g_hs[p * DIM];
#pragma unroll
    for (int j = 0; j < 16; j += 4) {
        float4 h;
        h.x = fmaxf(n1b[j + 0] + a.x * n1w[(j + 0) * 4] + a.y * n1w[(j + 0) * 4 + 1] +
                    a.z * n1w[(j + 0) * 4 + 2] + a.w * n1w[(j + 0) * 4 + 3], 0.0f);
        h.y = fmaxf(n1b[j + 1] + a.x * n1w[(j + 1) * 4] + a.y * n1w[(j + 1) * 4 + 1] +
                    a.z * n1w[(j + 1) * 4 + 2] + a.w * n1w[(j + 1) * 4 + 3], 0.0f);
        h.z = fmaxf(n1b[j + 2] + a.x * n1w[(j + 2) * 4] + a.y * n1w[(j + 2) * 4 + 1] +
                    a.z * n1w[(j + 2) * 4 + 2] + a.w * n1w[(j + 2) * 4 + 3], 0.0f);
        h.w = fmaxf(n1b[j + 3] + a.x * n1w[(j + 3) * 4] + a.y * n1w[(j + 3) * 4 + 1] +
                    a.z * n1w[(j + 3) * 4 + 2] + a.w * n1w[(j + 3) * 4 + 3], 0.0f);
        *(float4*)&hd[j] = h;
    }
}

// ---------------- fused per-round kernel -----------------------------------
// 128 threads = 32 nodes x 4 lanes (R15 structure).
// Phase 1 (r>0): msg-mean + root + ReLU + GRU (warp-local syncs).
// Phase 2: P via [d][k][jj] packed layout -> LDS.128 reads (4 per (d,kk)).
// Phase 3: R3's edge loop verbatim.
__global__ void __launch_bounds__(128) k_round(
    const float* __restrict__ b2,
    const float* __restrict__ cr, const float* __restrict__ cb,
    const float* __restrict__ wih, const float* __restrict__ whh,
    const float* __restrict__ bih, const float* __restrict__ bhh,
    const float* __restrict__ msg_r, float* __restrict__ msg_w, int r) {
    __shared__ __align__(16) ull s_w2p[2048];   // [d][k][jj-pair]: 16 KB
    __shared__ float s_b2[256];          // [d][k]
    __shared__ float s_cr[256];          // [d][k]
    __shared__ float s_wih[768];         // transposed [d][gate]
    __shared__ float s_whh[768];
    __shared__ float s_out[32][17];
    __shared__ float s_m[32][17];
    int tid = threadIdx.x;
    {   // stage packed w2 with 128b copies
        const ulonglong2* wg = (const ulonglong2*)g_w2p;
        ulonglong2* ws = (ulonglong2*)s_w2p;
        for (int i = tid; i < 1024; i += 128) ws[i] = wg[i];
    }
    for (int i = tid; i < 256; i += 128) { s_b2[i] = b2[i]; s_cr[i] = cr[i]; }
    for (int i = tid; i < 768; i += 128) {
        int rr = i >> 4, d = i & 15;
        s_wih[d * 48 + rr] = wih[i];
        s_whh[d * 48 + rr] = whh[i];
    }
    int nb = blockIdx.x * 32;
    for (int i = tid; i < 32 * DIM; i += 128) s_out[i >> 4][i & 15] = g_out[nb * DIM + i];
    __syncthreads();

    int l = tid & 3;                     // k-quad index
    int g = tid >> 2;                    // node within block
    int n = nb + g;

    if (r > 0) {
        // ---- fused update: mean(prev msgs) + root + ReLU + GRU ----
        int beg = g_dst_off[n], end = g_dst_off[n + 1];
        float4 a = make_float4(0.f, 0.f, 0.f, 0.f);
        float4 b = make_float4(0.f, 0.f, 0.f, 0.f);
        int q = beg;
        for (; q + 1 < end; q += 2) {
            float4 v0 = __ldg((const float4*)&msg_r[q * DIM + l * 4]);
            float4 v1 = __ldg((const float4*)&msg_r[(q + 1) * DIM + l * 4]);
            a.x += v0.x; a.y += v0.y; a.z += v0.z; a.w += v0.w;
            b.x += v1.x; b.y += v1.y; b.z += v1.z; b.w += v1.w;
        }
        if (q < end) {
            float4 v0 = __ldg((const float4*)&msg_r[q * DIM + l * 4]);
            a.x += v0.x; a.y += v0.y; a.z += v0.z; a.w += v0.w;
        }
        float id = g_invdeg[n];
        float sum4[4] = {a.x + b.x, a.y + b.y, a.z + b.z, a.w + b.w};
        float mloc[4];
#pragma unroll
        for (int kk = 0; kk < 4; ++kk) {
            int k = l * 4 + kk;
            float acc = sum4[kk] * id + cb[k];
#pragma unroll
            for (int d = 0; d < DIM; ++d) acc += s_out[g][d] * s_cr[d * 16 + k];
            mloc[kk] = fmaxf(acc, 0.0f);
        }
        __syncwarp();
#pragma unroll
        for (int kk = 0; kk < 4; ++kk) s_m[g][l * 4 + kk] = mloc[kk];
        __syncwarp();
        float hnew[4];
#pragma unroll
        for (int kk = 0; kk < 4; ++kk) {
            int k = l * 4 + kk;
            float gr = bih[k], gz = bih[k + 16], gn = bih[k + 32];
            float hr = bhh[k], hz = bhh[k + 16], hn = bhh[k + 32];
#pragma unroll
            for (int d = 0; d < DIM; ++d) {
                float md = s_m[g][d], hd = s_out[g][d];
                gr += md * s_wih[d * 48 + k];
                gz += md * s_wih[d * 48 + k + 16];
                gn += md * s_wih[d * 48 + k + 32];
                hr += hd * s_whh[d * 48 + k];
                hz += hd * s_whh[d * 48 + k + 16];
                hn += hd * s_whh[d * 48 + k + 32];
            }
            float rr = 1.0f / (1.0f + expf(-(gr + hr)));
            float zz = 1.0f / (1.0f + expf(-(gz + hz)));
            float nh = tanhf(gn + rr * hn);
            hnew[kk] = (1.0f - zz) * nh + zz * s_out[g][k];
        }
        __syncwarp();                    // all reads of s_out[g] complete
#pragma unroll
        for (int kk = 0; kk < 4; ++kk) {
            s_out[g][l * 4 + kk] = hnew[kk];
            g_out[n * DIM + l * 4 + kk] = hnew[kk];
        }
        __syncwarp();
    }

    // ---- P-compute: LDS.128 reads from [d][k][jj] layout ----
    ull p2[32];                          // [kk][jj]
    float xb[4];
#pragma unroll
    for (int i = 0; i < 32; ++i) p2[i] = 0ull;
#pragma unroll
    for (int kk = 0; kk < 4; ++kk) xb[kk] = 0.0f;
#pragma unroll
    for (int d = 0; d < 16; ++d) {
        float od = s_out[g][d];
        ull od2;
        asm("mov.b64 %0,{%1,%1};" : "=l"(od2) : "f"(od));
#pragma unroll
        for (int kk = 0; kk < 4; ++kk) {
            int k = l * 4 + kk;
            xb[kk] += od * s_b2[d * 16 + k];
            const ulonglong2* wp = (const ulonglong2*)&s_w2p[(d * 16 + k) * 8];
            ulonglong2 wA = wp[0], wB = wp[1], wC = wp[2], wD = wp[3];
            asm("fma.rn.f32x2 %0,%1,%2,%0;" : "+l"(p2[kk * 8 + 0]) : "l"(od2), "l"(wA.x));
            asm("fma.rn.f32x2 %0,%1,%2,%0;" : "+l"(p2[kk * 8 + 1]) : "l"(od2), "l"(wA.y));
            asm("fma.rn.f32x2 %0,%1,%2,%0;" : "+l"(p2[kk * 8 + 2]) : "l"(od2), "l"(wB.x));
            asm("fma.rn.f32x2 %0,%1,%2,%0;" : "+l"(p2[kk * 8 + 3]) : "l"(od2), "l"(wB.y));
            asm("fma.rn.f32x2 %0,%1,%2,%0;" : "+l"(p2[kk * 8 + 4]) : "l"(od2), "l"(wC.x));
            asm("fma.rn.f32x2 %0,%1,%2,%0;" : "+l"(p2[kk * 8 + 5]) : "l"(od2), "l"(wC.y));
            asm("fma.rn.f32x2 %0,%1,%2,%0;" : "+l"(p2[kk * 8 + 6]) : "l"(od2), "l"(wD.x));
            asm("fma.rn.f32x2 %0,%1,%2,%0;" : "+l"(p2[kk * 8 + 7]) : "l"(od2), "l"(wD.y));
        }
    }

    // ---- edge mainloop (unchanged) ----
    int beg = g_src_off[n], end = g_src_off[n + 1];
    const ulonglong2* hsp = (const ulonglong2*)g_hs;
    for (int i = beg; i < end; ++i) {
        int q = __ldg(&g_qs[i]);
        ulonglong2 A = hsp[i * 4 + 0], B = hsp[i * 4 + 1];
        ulonglong2 C = hsp[i * 4 + 2], D = hsp[i * 4 + 3];
        float4 m4;
        float* mm = (float*)&m4;
#pragma unroll
        for (int kk = 0; kk < 4; ++kk) {
            ull acc;
            asm("mul.rn.f32x2 %0,%1,%2;" : "=l"(acc) : "l"(A.x), "l"(p2[kk * 8 + 0]));
            asm("fma.rn.f32x2 %0,%1,%2,%0;" : "+l"(acc) : "l"(A.y), "l"(p2[kk * 8 + 1]));
            asm("fma.rn.f32x2 %0,%1,%2,%0;" : "+l"(acc) : "l"(B.x), "l"(p2[kk * 8 + 2]));
            asm("fma.rn.f32x2 %0,%1,%2,%0;" : "+l"(acc) : "l"(B.y), "l"(p2[kk * 8 + 3]));
            asm("fma.rn.f32x2 %0,%1,%2,%0;" : "+l"(acc) : "l"(C.x), "l"(p2[kk * 8 + 4]));
            asm("fma.rn.f32x2 %0,%1,%2,%0;" : "+l"(acc) : "l"(C.y), "l"(p2[kk * 8 + 5]));
            asm("fma.rn.f32x2 %0,%1,%2,%0;" : "+l"(acc) : "l"(D.x), "l"(p2[kk * 8 + 6]));
            asm("fma.rn.f32x2 %0,%1,%2,%0;" : "+l"(acc) : "l"(D.y), "l"(p2[kk * 8 + 7]));
            float lo, hi;
            asm("mov.b64 {%0,%1},%2;" : "=f"(lo), "=f"(hi) : "l"(acc));
            mm[kk] = lo + hi + xb[kk];
        }
        ((float4*)msg_w)[q * 4 + l] = m4;    // 64B per edge
    }
}

// ---------------- final update -> d_out ----------------
__global__ void k_fin(const float* __restrict__ msg_r,
                      const float* __restrict__ cr, const float* __restrict__ cb,
                      const float* __restrict__ wih, const float* __restrict__ whh,
                      const float* __restrict__ bih, const float* __restrict__ bhh,
                      float* __restrict__ outw) {
    __shared__ float s_cr[DIM * DIM];
    __shared__ float s_wih[DIM * 3 * DIM];   // transposed [d][gate]
    __shared__ float s_whh[DIM * 3 * DIM];
    __shared__ float s_out[16][DIM];
    __shared__ float s_m[16][DIM];
    int tid = threadIdx.x;
    for (int i = tid; i < DIM * DIM; i += 256) s_cr[i] = cr[i];
    for (int i = tid; i < 3 * DIM * DIM; i += 256) {
        int r = i >> 4, d = i & 15;
        s_wih[d * 48 + r] = wih[i];
        s_whh[d * 48 + r] = whh[i];
    }
    int ln = tid >> 4, k = tid & 15;
    int n = blockIdx.x * 16 + ln;
    float hprev = g_out[n * DIM + k];
    s_out[ln][k] = hprev;
    __syncthreads();

    int beg = g_dst_off[n], end = g_dst_off[n + 1];
    float a0 = 0.0f, a1 = 0.0f, a2 = 0.0f, a3 = 0.0f;
    int q = beg;
    for (; q + 3 < end; q += 4) {
        a0 += __ldg(&msg_r[(q + 0) * DIM + k]);
        a1 += __ldg(&msg_r[(q + 1) * DIM + k]);
        a2 += __ldg(&msg_r[(q + 2) * DIM + k]);
        a3 += __ldg(&msg_r[(q + 3) * DIM + k]);
    }
    for (; q < end; ++q) a0 += __ldg(&msg_r[q * DIM + k]);
    float acc = ((a0 + a1) + (a2 + a3)) * g_invdeg[n] + cb[k];
#pragma unroll
    for (int d = 0; d < DIM; ++d) acc += s_out[ln][d] * s_cr[d * DIM + k];
    float m = fmaxf(acc, 0.0f);
    s_m[ln][k] = m;
    __syncthreads();

    float gr = bih[k], gz = bih[k + 16], gn = bih[k + 32];
    float hr = bhh[k], hz = bhh[k + 16], hn = bhh[k + 32];
#pragma unroll
    for (int d = 0; d < DIM; ++d) {
        float md = s_m[ln][d], hd = s_out[ln][d];
        gr += md * s_wih[d * 48 + k];
        gz += md * s_wih[d * 48 + k + 16];
        gn += md * s_wih[d * 48 + k + 32];
        hr += hd * s_whh[d * 48 + k];
        hz += hd * s_whh[d * 48 + k + 16];
        hn += hd * s_whh[d * 48 + k + 32];
    }
    float r = 1.0f / (1.0f + expf(-(gr + hr)));
    float z = 1.0f / (1.0f + expf(-(gz + hz)));
    float nh = tanhf(gn + r * hn);
    outw[n * DIM + k] = (1.0f - z) * nh + z * hprev;
}

// ---------------- host launcher ----------------
extern "C" void kernel_launch(void* const* d_in, const int* in_sizes, int n_in,
                              void* d_out, int out_size) {
    const float* x         = (const float*)d_in[0];
    const int*   ei        = (const int*)  d_in[1];
    const float* ea        = (const float*)d_in[2];
    const float* lin0_w    = (const float*)d_in[3];
    const float* lin0_b    = (const float*)d_in[4];
    const float* nn1_w     = (const float*)d_in[5];
    const float* nn1_b     = (const float*)d_in[6];
    const float* nn2_w     = (const float*)d_in[7];
    const float* nn2_b     = (const float*)d_in[8];
    const float* conv_root = (const float*)d_in[9];
    const float* conv_bias = (const float*)d_in[10];
    const float* w_ih      = (const float*)d_in[11];
    const float* w_hh      = (const float*)d_in[12];
    const float* b_ih      = (const float*)d_in[13];
    const float* b_hh      = (const float*)d_in[14];

    float *m0 = nullptr, *m1 = nullptr;
    cudaGetSymbolAddress((void**)&m0, g_msg0);
    cudaGetSymbolAddress((void**)&m1, g_msg1);

    k_hist<<<N_EDGES / 256 + (N_NODES * DIM) / 256, 256>>>(x, ei, lin0_w, lin0_b);
    k_scan<<<3, 1024>>>(nn2_w);
    k_scatter<<<(N_EDGES + 255) / 256, 256>>>(ei, ea, nn1_w, nn1_b);

    // k_round r: (r>0) update with round r-1 msgs, then emit round r msgs.
    // r writes m[r&1]; k_fin consumes round-5 msgs (m1) -> d_out.
    for (int r = 0; r < 6; ++r) {
        const float* mr = ((r - 1) & 1) ? m1 : m0;
        float* mw = (r & 1) ? m1 : m0;
        k_round<<<N_NODES / 32, 128>>>(nn2_b, conv_root, conv_bias,
                                       w_ih, w_hh, b_ih, b_hh, mr, mw, r);
    }
    k_fin<<<N_NODES / 16, 256>>>(m1, conv_root, conv_bias, w_ih, w_hh,
                                 b_ih, b_hh, (float*)d_out);
}

// round 17
// speedup vs baseline: 1.4864x; 1.4864x over previous
#include <cuda_runtime.h>
#include <math.h>
#include <stdint.h>

#define N_NODES 12800
#define N_EDGES 204800
#define DIM 16

typedef unsigned long long ull;

// ---------------- scratch (static device memory, no allocs) ----------------
__device__ float g_out[N_NODES * DIM];
__device__ float g_hs[N_EDGES * DIM];       // edge hidden, src-sorted order
__device__ int   g_qs[N_EDGES];             // src-sorted slot -> dst-sorted slot
__device__ float g_msg0[N_EDGES * DIM];     // message ping-pong (dst-sorted)
__device__ float g_msg1[N_EDGES * DIM];
__device__ int   g_src_cnt[N_NODES];        // zero at load; re-zeroed by k_scan
__device__ int   g_dst_cnt[N_NODES];        // zero at load; re-zeroed by k_scan
__device__ int   g_src_off[N_NODES + 1];
__device__ int   g_dst_off[N_NODES + 1];
__device__ int   g_src_cur[N_NODES];
__device__ int   g_dst_cur[N_NODES];
__device__ float g_invdeg[N_NODES];

// ---------------- setup ----------------
// blocks [0,800): edge histograms; blocks [800,1600): lin0.
__global__ void k_hist(const float* __restrict__ x, const int* __restrict__ ei,
                       const float* __restrict__ l0w, const float* __restrict__ l0b) {
    int gb = blockIdx.x;
    if (gb < N_EDGES / 256) {
        int e = gb * 256 + threadIdx.x;
        atomicAdd(&g_src_cnt[ei[e]], 1);
        atomicAdd(&g_dst_cnt[ei[N_EDGES + e]], 1);
    } else {
        int i = (gb - N_EDGES / 256) * 256 + threadIdx.x;
        int n = i >> 4, k = i & 15;
        float acc = l0b[k];
#pragma unroll
        for (int c = 0; c < 3; ++c) acc += x[n * 3 + c] * l0w[k * 3 + c];
        g_out[i] = fmaxf(acc, 0.0f);
    }
}

// Shuffle-based exclusive scans: block 0 = src counts, block 1 = dst (+invdeg).
// Both re-zero their count arrays for the next kernel_launch call.
__global__ void k_scan() {
    const int PER = 13;
    int which = blockIdx.x;
    int* cnt = which ? g_dst_cnt : g_src_cnt;
    int* off = which ? g_dst_off : g_src_off;
    int* cur = which ? g_dst_cur : g_src_cur;
    int tid = threadIdx.x, lane = tid & 31, wid = tid >> 5;
    int base = tid * PER;
    int c[PER];
    int local = 0;
#pragma unroll
    for (int i = 0; i < PER; ++i) {
        int idx = base + i;
        c[i] = (idx < N_NODES) ? cnt[idx] : 0;
        local += c[i];
    }
    int incl = local;
#pragma unroll
    for (int s = 1; s < 32; s <<= 1) {
        int v = __shfl_up_sync(0xffffffffu, incl, s);
        if (lane >= s) incl += v;
    }
    __shared__ int wsum[32];
    if (lane == 31) wsum[wid] = incl;
    __syncthreads();
    if (wid == 0) {
        int v = wsum[lane], iv = v;
#pragma unroll
        for (int s = 1; s < 32; s <<= 1) {
            int t = __shfl_up_sync(0xffffffffu, iv, s);
            if (lane >= s) iv += t;
        }
        wsum[lane] = iv - v;
    }
    __syncthreads();
    int run = wsum[wid] + (incl - local);
#pragma unroll
    for (int i = 0; i < PER; ++i) {
        int idx = base + i;
        if (idx < N_NODES) {
            off[idx] = run;
            cur[idx] = run;
            if (which) g_invdeg[idx] = 1.0f / fmaxf((float)c[i], 1.0f);
            cnt[idx] = 0;                    // re-zero for next call
            run += c[i];
        }
    }
    if (tid == 1023) off[N_NODES] = run;
}

// Per edge: place into src-sorted slot p, record its dst-sorted slot q,
// compute edge hidden h = relu(ea @ nn1_w^T + nn1_b) directly into g_hs[p].
__global__ void k_scatter(const int* __restrict__ ei, const float* __restrict__ ea,
                          const float* __restrict__ n1w, const float* __restrict__ n1b) {
    int e = blockIdx.x * blockDim.x + threadIdx.x;
    if (e >= N_EDGES) return;
    int s = ei[e], d = ei[N_EDGES + e];
    int p = atomicAdd(&g_src_cur[s], 1);
    int q = atomicAdd(&g_dst_cur[d], 1);
    g_qs[p] = q;
    float4 a = __ldg((const float4*)&ea[e * 4]);
    float* hd = &g_hs[p * DIM];
#pragma unroll
    for (int j = 0; j < 16; j += 4) {
        float4 h;
        h.x = fmaxf(n1b[j + 0] + a.x * n1w[(j + 0) * 4] + a.y * n1w[(j + 0) * 4 + 1] +
                    a.z * n1w[(j + 0) * 4 + 2] + a.w * n1w[(j + 0) * 4 + 3], 0.0f);
        h.y = fmaxf(n1b[j + 1] + a.x * n1w[(j + 1) * 4] + a.y * n1w[(j + 1) * 4 + 1] +
                    a.z * n1w[(j + 1) * 4 + 2] + a.w * n1w[(j + 1) * 4 + 3], 0.0f);
        h.z = fmaxf(n1b[j + 2] + a.x * n1w[(j + 2) * 4] + a.y * n1w[(j + 2) * 4 + 1] +
                    a.z * n1w[(j + 2) * 4 + 2] + a.w * n1w[(j + 2) * 4 + 3], 0.0f);
        h.w = fmaxf(n1b[j + 3] + a.x * n1w[(j + 3) * 4] + a.y * n1w[(j + 3) * 4 + 1] +
                    a.z * n1w[(j + 3) * 4 + 2] + a.w * n1w[(j + 3) * 4 + 3], 0.0f);
        *(float4*)&hd[j] = h;
    }
}

// ---------------- fused per-round kernel -----------------------------------
// 128 threads = 32 nodes x 4 lanes (R15 structure, unchanged except
// prefetched q in the edge mainloop).
__global__ void __launch_bounds__(128) k_round(
    const float* __restrict__ w2, const float* __restrict__ b2,
    const float* __restrict__ cr, const float* __restrict__ cb,
    const float* __restrict__ wih, const float* __restrict__ whh,
    const float* __restrict__ bih, const float* __restrict__ bhh,
    const float* __restrict__ msg_r, float* __restrict__ msg_w, int r) {
    __shared__ ull s_w2p[16 * 8 * 16];   // [d][jj][k], j-pairs packed, 16KB
    __shared__ float s_b2[256];          // [d][k]
    __shared__ float s_cr[256];          // [d][k]
    __shared__ float s_wih[768];         // transposed [d][gate]
    __shared__ float s_whh[768];
    __shared__ float s_out[32][17];
    __shared__ float s_m[32][17];
    int tid = threadIdx.x;
    for (int i = tid; i < 4096; i += 128) {
        int d = i >> 8, k = (i >> 4) & 15, j = i & 15;
        ((float*)&s_w2p[(d * 8 + (j >> 1)) * 16 + k])[j & 1] = w2[i];
    }
    for (int i = tid; i < 256; i += 128) { s_b2[i] = b2[i]; s_cr[i] = cr[i]; }
    for (int i = tid; i < 768; i += 128) {
        int rr = i >> 4, d = i & 15;
        s_wih[d * 48 + rr] = wih[i];
        s_whh[d * 48 + rr] = whh[i];
    }
    int nb = blockIdx.x * 32;
    for (int i = tid; i < 32 * DIM; i += 128) s_out[i >> 4][i & 15] = g_out[nb * DIM + i];
    __syncthreads();

    int l = tid & 3;                     // k-quad index
    int g = tid >> 2;                    // node within block
    int n = nb + g;

    if (r > 0) {
        // ---- fused update: mean(prev msgs) + root + ReLU + GRU ----
        int beg = g_dst_off[n], end = g_dst_off[n + 1];
        float4 a = make_float4(0.f, 0.f, 0.f, 0.f);
        float4 b = make_float4(0.f, 0.f, 0.f, 0.f);
        int q = beg;
        for (; q + 1 < end; q += 2) {
            float4 v0 = __ldg((const float4*)&msg_r[q * DIM + l * 4]);
            float4 v1 = __ldg((const float4*)&msg_r[(q + 1) * DIM + l * 4]);
            a.x += v0.x; a.y += v0.y; a.z += v0.z; a.w += v0.w;
            b.x += v1.x; b.y += v1.y; b.z += v1.z; b.w += v1.w;
        }
        if (q < end) {
            float4 v0 = __ldg((const float4*)&msg_r[q * DIM + l * 4]);
            a.x += v0.x; a.y += v0.y; a.z += v0.z; a.w += v0.w;
        }
        float id = g_invdeg[n];
        float sum4[4] = {a.x + b.x, a.y + b.y, a.z + b.z, a.w + b.w};
        float mloc[4];
#pragma unroll
        for (int kk = 0; kk < 4; ++kk) {
            int k = l * 4 + kk;
            float acc = sum4[kk] * id + cb[k];
#pragma unroll
            for (int d = 0; d < DIM; ++d) acc += s_out[g][d] * s_cr[d * 16 + k];
            mloc[kk] = fmaxf(acc, 0.0f);
        }
        __syncwarp();
#pragma unroll
        for (int kk = 0; kk < 4; ++kk) s_m[g][l * 4 + kk] = mloc[kk];
        __syncwarp();
        float hnew[4];
#pragma unroll
        for (int kk = 0; kk < 4; ++kk) {
            int k = l * 4 + kk;
            float gr = bih[k], gz = bih[k + 16], gn = bih[k + 32];
            float hr = bhh[k], hz = bhh[k + 16], hn = bhh[k + 32];
#pragma unroll
            for (int d = 0; d < DIM; ++d) {
                float md = s_m[g][d], hd = s_out[g][d];
                gr += md * s_wih[d * 48 + k];
                gz += md * s_wih[d * 48 + k + 16];
                gn += md * s_wih[d * 48 + k + 32];
                hr += hd * s_whh[d * 48 + k];
                hz += hd * s_whh[d * 48 + k + 16];
                hn += hd * s_whh[d * 48 + k + 32];
            }
            float rr = 1.0f / (1.0f + expf(-(gr + hr)));
            float zz = 1.0f / (1.0f + expf(-(gz + hz)));
            float nh = tanhf(gn + rr * hn);
            hnew[kk] = (1.0f - zz) * nh + zz * s_out[g][k];
        }
        __syncwarp();                    // all reads of s_out[g] complete
#pragma unroll
        for (int kk = 0; kk < 4; ++kk) {
            s_out[g][l * 4 + kk] = hnew[kk];
            g_out[n * DIM + l * 4 + kk] = hnew[kk];
        }
        __syncwarp();
    }

    // ---- P-compute: P[k][j-pairs] as 32 packed f32x2 regs ----
    ull p2[32];                          // [kk][jj]
    float xb[4];
#pragma unroll
    for (int i = 0; i < 32; ++i) p2[i] = 0ull;
#pragma unroll
    for (int kk = 0; kk < 4; ++kk) xb[kk] = 0.0f;
#pragma unroll
    for (int d = 0; d < 16; ++d) {
        float od = s_out[g][d];
        ull od2;
        asm("mov.b64 %0,{%1,%1};" : "=l"(od2) : "f"(od));
#pragma unroll
        for (int kk = 0; kk < 4; ++kk) {
            int k = l * 4 + kk;
            xb[kk] += od * s_b2[d * 16 + k];
#pragma unroll
            for (int jj = 0; jj < 8; ++jj) {
                ull w = s_w2p[(d * 8 + jj) * 16 + k];
                asm("fma.rn.f32x2 %0,%1,%2,%0;" : "+l"(p2[kk * 8 + jj]) : "l"(od2), "l"(w));
            }
        }
    }

    // ---- edge mainloop (R15 + prefetched q) ----
    int beg = g_src_off[n], end = g_src_off[n + 1];
    const ulonglong2* hsp = (const ulonglong2*)g_hs;
    if (beg < end) {
        int q = __ldg(&g_qs[beg]);
        for (int i = beg; i < end; ++i) {
            int ip = (i + 1 < end) ? i + 1 : i;
            int qn = __ldg(&g_qs[ip]);           // prefetch next store slot
            ulonglong2 A = hsp[i * 4 + 0], B = hsp[i * 4 + 1];
            ulonglong2 C = hsp[i * 4 + 2], D = hsp[i * 4 + 3];
            float4 m4;
            float* mm = (float*)&m4;
#pragma unroll
            for (int kk = 0; kk < 4; ++kk) {
                ull acc;
                asm("mul.rn.f32x2 %0,%1,%2;" : "=l"(acc) : "l"(A.x), "l"(p2[kk * 8 + 0]));
                asm("fma.rn.f32x2 %0,%1,%2,%0;" : "+l"(acc) : "l"(A.y), "l"(p2[kk * 8 + 1]));
                asm("fma.rn.f32x2 %0,%1,%2,%0;" : "+l"(acc) : "l"(B.x), "l"(p2[kk * 8 + 2]));
                asm("fma.rn.f32x2 %0,%1,%2,%0;" : "+l"(acc) : "l"(B.y), "l"(p2[kk * 8 + 3]));
                asm("fma.rn.f32x2 %0,%1,%2,%0;" : "+l"(acc) : "l"(C.x), "l"(p2[kk * 8 + 4]));
                asm("fma.rn.f32x2 %0,%1,%2,%0;" : "+l"(acc) : "l"(C.y), "l"(p2[kk * 8 + 5]));
                asm("fma.rn.f32x2 %0,%1,%2,%0;" : "+l"(acc) : "l"(D.x), "l"(p2[kk * 8 + 6]));
                asm("fma.rn.f32x2 %0,%1,%2,%0;" : "+l"(acc) : "l"(D.y), "l"(p2[kk * 8 + 7]));
                float lo, hi;
                asm("mov.b64 {%0,%1},%2;" : "=f"(lo), "=f"(hi) : "l"(acc));
                mm[kk] = lo + hi + xb[kk];
            }
            ((float4*)msg_w)[q * 4 + l] = m4;    // 64B per edge
            q = qn;
        }
    }
}

// ---------------- final update -> d_out ----------------
__global__ void k_fin(const float* __restrict__ msg_r,
                      const float* __restrict__ cr, const float* __restrict__ cb,
                      const float* __restrict__ wih, const float* __restrict__ whh,
                      const float* __restrict__ bih, const float* __restrict__ bhh,
                      float* __restrict__ outw) {
    __shared__ float s_cr[DIM * DIM];
    __shared__ float s_wih[DIM * 3 * DIM];   // transposed [d][gate]
    __shared__ float s_whh[DIM * 3 * DIM];
    __shared__ float s_out[16][DIM];
    __shared__ float s_m[16][DIM];
    int tid = threadIdx.x;
    for (int i = tid; i < DIM * DIM; i += 256) s_cr[i] = cr[i];
    for (int i = tid; i < 3 * DIM * DIM; i += 256) {
        int r = i >> 4, d = i & 15;
        s_wih[d * 48 + r] = wih[i];
        s_whh[d * 48 + r] = whh[i];
    }
    int ln = tid >> 4, k = tid & 15;
    int n = blockIdx.x * 16 + ln;
    float hprev = g_out[n * DIM + k];
    s_out[ln][k] = hprev;
    __syncthreads();

    int beg = g_dst_off[n], end = g_dst_off[n + 1];
    float a0 = 0.0f, a1 = 0.0f, a2 = 0.0f, a3 = 0.0f;
    int q = beg;
    for (; q + 3 < end; q += 4) {
        a0 += __ldg(&msg_r[(q + 0) * DIM + k]);
        a1 += __ldg(&msg_r[(q + 1) * DIM + k]);
        a2 += __ldg(&msg_r[(q + 2) * DIM + k]);
        a3 += __ldg(&msg_r[(q + 3) * DIM + k]);
    }
    for (; q < end; ++q) a0 += __ldg(&msg_r[q * DIM + k]);
    float acc = ((a0 + a1) + (a2 + a3)) * g_invdeg[n] + cb[k];
#pragma unroll
    for (int d = 0; d < DIM; ++d) acc += s_out[ln][d] * s_cr[d * DIM + k];
    float m = fmaxf(acc, 0.0f);
    s_m[ln][k] = m;
    __syncthreads();

    float gr = bih[k], gz = bih[k + 16], gn = bih[k + 32];
    float hr = bhh[k], hz = bhh[k + 16], hn = bhh[k + 32];
#pragma unroll
    for (int d = 0; d < DIM; ++d) {
        float md = s_m[ln][d], hd = s_out[ln][d];
        gr += md * s_wih[d * 48 + k];
        gz += md * s_wih[d * 48 + k + 16];
        gn += md * s_wih[d * 48 + k + 32];
        hr += hd * s_whh[d * 48 + k];
        hz += hd * s_whh[d * 48 + k + 16];
        hn += hd * s_whh[d * 48 + k + 32];
    }
    float r = 1.0f / (1.0f + expf(-(gr + hr)));
    float z = 1.0f / (1.0f + expf(-(gz + hz)));
    float nh = tanhf(gn + r * hn);
    outw[n * DIM + k] = (1.0f - z) * nh + z * hprev;
}

// ---------------- host launcher ----------------
extern "C" void kernel_launch(void* const* d_in, const int* in_sizes, int n_in,
                              void* d_out, int out_size) {
    const float* x         = (const float*)d_in[0];
    const int*   ei        = (const int*)  d_in[1];
    const float* ea        = (const float*)d_in[2];
    const float* lin0_w    = (const float*)d_in[3];
    const float* lin0_b    = (const float*)d_in[4];
    const float* nn1_w     = (const float*)d_in[5];
    const float* nn1_b     = (const float*)d_in[6];
    const float* nn2_w     = (const float*)d_in[7];
    const float* nn2_b     = (const float*)d_in[8];
    const float* conv_root = (const float*)d_in[9];
    const float* conv_bias = (const float*)d_in[10];
    const float* w_ih      = (const float*)d_in[11];
    const float* w_hh      = (const float*)d_in[12];
    const float* b_ih      = (const float*)d_in[13];
    const float* b_hh      = (const float*)d_in[14];

    float *m0 = nullptr, *m1 = nullptr;
    cudaGetSymbolAddress((void**)&m0, g_msg0);
    cudaGetSymbolAddress((void**)&m1, g_msg1);

    k_hist<<<N_EDGES / 256 + (N_NODES * DIM) / 256, 256>>>(x, ei, lin0_w, lin0_b);
    k_scan<<<2, 1024>>>();
    k_scatter<<<(N_EDGES + 255) / 256, 256>>>(ei, ea, nn1_w, nn1_b);

    // k_round r: (r>0) update with round r-1 msgs, then emit round r msgs.
    // r writes m[r&1]; k_fin consumes round-5 msgs (m1) -> d_out.
    for (int r = 0; r < 6; ++r) {
        const float* mr = ((r - 1) & 1) ? m1 : m0;
        float* mw = (r & 1) ? m1 : m0;
        k_round<<<N_NODES / 32, 128>>>(nn2_w, nn2_b, conv_root, conv_bias,
                                       w_ih, w_hh, b_ih, b_hh, mr, mw, r);
    }
    k_fin<<<N_NODES / 16, 256>>>(m1, conv_root, conv_bias, w_ih, w_hh,
                                 b_ih, b_hh, (float*)d_out);
}